// round 7
// baseline (speedup 1.0000x reference)
#include <cuda_runtime.h>

#define BB 4
#define TT 4096
#define CC 1024
#define HH 128
#define SCALE 0.03125f              // C^-0.5 = 1/32
#define GAMMA 0.96875f
#define INVG  (1.0f / 0.96875f)
#define L2G  (-0.0458036929f)       // log2(0.96875)
#define NPAST 4                     // past key tiles of 128; dropped mass ~1e-7 rel

typedef unsigned long long u64;

// packed fp32x2 helpers (Blackwell f32x2 ops; ptxas never emits these itself)
__device__ __forceinline__ u64 f2pack(float lo, float hi) {
    u64 r; asm("mov.b64 %0, {%1, %2};" : "=l"(r) : "f"(lo), "f"(hi)); return r;
}
__device__ __forceinline__ u64 f2dup(float v) {
    u64 r; asm("mov.b64 %0, {%1, %1};" : "=l"(r) : "f"(v)); return r;
}
__device__ __forceinline__ u64 f2fma(u64 a, u64 b, u64 c) {
    u64 d; asm("fma.rn.f32x2 %0, %1, %2, %3;" : "=l"(d) : "l"(a), "l"(b), "l"(c)); return d;
}
__device__ __forceinline__ u64 f2mul(u64 a, u64 b) {
    u64 d; asm("mul.rn.f32x2 %0, %1, %2;" : "=l"(d) : "l"(a), "l"(b)); return d;
}
__device__ __forceinline__ float2 f2unpack(u64 v) {
    float lo, hi; asm("mov.b64 {%0, %1}, %2;" : "=f"(lo), "=f"(hi) : "l"(v));
    return make_float2(lo, hi);
}

// Scratch for q,k,v projections: [B*T, H] each (8 MB each). No allocation APIs.
__device__ float g_q[BB * TT * HH];
__device__ float g_k[BB * TT * HH];
__device__ float g_v[BB * TT * HH];

__device__ __forceinline__ void cp_async16(float* s, const float* g) {
    unsigned sa = (unsigned)__cvta_generic_to_shared(s);
    asm volatile("cp.async.ca.shared.global [%0], [%1], 16;\n" :: "r"(sa), "l"(g));
}
__device__ __forceinline__ void cp_commit() {
    asm volatile("cp.async.commit_group;\n");
}
template <int N>
__device__ __forceinline__ void cp_wait() {
    asm volatile("cp.async.wait_group %0;\n" :: "n"(N));
}

// ---------------------------------------------------------------------------
// QKV projection GEMM: out[M=16384, 128] = x[16384, 1024] @ W[1024, 128]
// grid: (128 row-tiles, 3 weights), 256 threads, 8x8 micro-tile computed as
// 8x4 packed f32x2 accumulators. cp.async double-buffered BK=32. 2 CTAs/SM.
// ---------------------------------------------------------------------------
__global__ __launch_bounds__(256, 2) void qkv_kernel(
    const float* __restrict__ x, const float* __restrict__ Wq,
    const float* __restrict__ Wk, const float* __restrict__ Wv)
{
    extern __shared__ float sm[];
    float* xs = sm;               // [2][128][32]
    float* ws = sm + 2 * 4096;    // [2][32][128]

    const float* W    = (blockIdx.y == 0) ? Wq : (blockIdx.y == 1 ? Wk : Wv);
    float*       outp = (blockIdx.y == 0) ? g_q : (blockIdx.y == 1 ? g_k : g_v);

    const int row0 = blockIdx.x * 128;
    const int tid  = threadIdx.x;
    const int tx   = tid & 15;
    const int ty   = tid >> 4;

    auto issue = [&](int kt, int buf) {
        const int k0 = kt * 32;
        #pragma unroll
        for (int i = 0; i < 4; i++) {          // x tile: 128x32 floats
            int idx = tid + i * 256;
            int r = idx >> 3, kq = (idx & 7) << 2;
            cp_async16(xs + buf * 4096 + r * 32 + kq,
                       x + (size_t)(row0 + r) * CC + k0 + kq);
        }
        #pragma unroll
        for (int i = 0; i < 4; i++) {          // W tile: 32x128 floats
            int idx = tid + i * 256;
            int kr = idx >> 5, cq = (idx & 31) << 2;
            cp_async16(ws + buf * 4096 + kr * 128 + cq,
                       W + (size_t)(k0 + kr) * HH + cq);
        }
        cp_commit();
    };

    u64 acc2[8][4];
    #pragma unroll
    for (int i = 0; i < 8; i++)
        #pragma unroll
        for (int p = 0; p < 4; p++) acc2[i][p] = 0ull;

    issue(0, 0);
    for (int kt = 0; kt < CC / 32; ++kt) {
        const int cur = kt & 1;
        if (kt + 1 < CC / 32) { issue(kt + 1, cur ^ 1); cp_wait<1>(); }
        else                  { cp_wait<0>(); }
        __syncthreads();

        const float* xb = xs + cur * 4096;
        const float* wb = ws + cur * 4096;
        #pragma unroll
        for (int kk = 0; kk < 32; kk += 2) {
            // x broadcasts for kk and kk+1 loaded as contiguous float2
            u64 a2lo[8], a2hi[8];
            #pragma unroll
            for (int i = 0; i < 8; i++) {
                float2 xv = *(const float2*)(xb + (ty * 8 + i) * 32 + kk);
                a2lo[i] = f2dup(xv.x);
                a2hi[i] = f2dup(xv.y);
            }
            {
                const ulonglong2* bp = (const ulonglong2*)(wb + kk * 128 + tx * 8);
                ulonglong2 bl0 = bp[0], bl1 = bp[1];
                u64 b2[4] = {bl0.x, bl0.y, bl1.x, bl1.y};
                #pragma unroll
                for (int i = 0; i < 8; i++)
                    #pragma unroll
                    for (int p = 0; p < 4; p++)
                        acc2[i][p] = f2fma(a2lo[i], b2[p], acc2[i][p]);
            }
            {
                const ulonglong2* bp = (const ulonglong2*)(wb + (kk + 1) * 128 + tx * 8);
                ulonglong2 bl0 = bp[0], bl1 = bp[1];
                u64 b2[4] = {bl0.x, bl0.y, bl1.x, bl1.y};
                #pragma unroll
                for (int i = 0; i < 8; i++)
                    #pragma unroll
                    for (int p = 0; p < 4; p++)
                        acc2[i][p] = f2fma(a2hi[i], b2[p], acc2[i][p]);
            }
        }
        __syncthreads();
    }

    #pragma unroll
    for (int i = 0; i < 8; i++) {
        ulonglong2* op = (ulonglong2*)(outp + (size_t)(row0 + ty * 8 + i) * HH + tx * 8);
        op[0] = make_ulonglong2(acc2[i][0], acc2[i][1]);
        op[1] = make_ulonglong2(acc2[i][2], acc2[i][3]);
    }
}

// ---------------------------------------------------------------------------
// Banded retention, one 128-row Q tile per CTA, <=5 key tiles, f32x2 packed.
// tx = tid&15 -> Q-row block (n = tx*8+i), ty = tid>>4 -> K-row / H-col block.
// smem: qs_t [h][n] swizzled (64K) + kvs k-then-v row-major (64K)
//       + ss_t [m][n] (64K) = 192 KB -> 1 CTA/SM, 128 CTAs = one wave.
// ---------------------------------------------------------------------------
__device__ __forceinline__ int qswz(int h, int r) {
    return h * 128 + ((((r >> 3) ^ ((h >> 2) & 15)) << 3) | (r & 7));
}

__global__ __launch_bounds__(256, 1) void attn_kernel(float* __restrict__ out)
{
    extern __shared__ float sm[];
    float* qs  = sm;            // swizzled q^T [128 h][128 n]
    float* kvs = sm + 16384;    // [128][128] (k, then v) row-major
    float* ss  = sm + 32768;    // S^T: [128 m][128 n]

    const int b   = blockIdx.y;
    const int bx  = blockIdx.x;
    const int n0  = bx * 128;
    const int tid = threadIdx.x;
    const int tx  = tid & 15;
    const int ty  = tid >> 4;

    // q load + transpose + swizzle (once per CTA)
    const float* qg = g_q + ((size_t)b * TT + n0) * HH;
    #pragma unroll
    for (int i = 0; i < 16; i++) {
        int idx = tid + i * 256;
        int r = idx >> 5, c = (idx & 31) << 2;
        float4 v4 = *(const float4*)(qg + r * 128 + c);
        qs[qswz(c + 0, r)] = v4.x;
        qs[qswz(c + 1, r)] = v4.y;
        qs[qswz(c + 2, r)] = v4.z;
        qs[qswz(c + 3, r)] = v4.w;
    }

    u64 o2[8][4];   // O[n = tx*8+i][h pair p: ty*8+2p, +2p+1]
    #pragma unroll
    for (int i = 0; i < 8; i++)
        #pragma unroll
        for (int p = 0; p < 4; p++) o2[i][p] = 0ull;

    // gamma^i and gamma^-j tables
    float gp[8], gn[8];
    gp[0] = 1.0f; gn[0] = 1.0f;
    #pragma unroll
    for (int i = 1; i < 8; i++) { gp[i] = gp[i-1] * GAMMA; gn[i] = gn[i-1] * INVG; }

    int mt0 = bx - NPAST; if (mt0 < 0) mt0 = 0;

    for (int mt = mt0; mt <= bx; ++mt) {
        const int m0 = mt * 128;
        __syncthreads();   // q stores visible (iter0) / prev phase-B reads done

        // k tile -> kvs (row-major, coalesced)
        const float* kg = g_k + ((size_t)b * TT + m0) * HH;
        #pragma unroll
        for (int i = 0; i < 16; i++) {
            int pos = (tid + i * 256) * 4;
            *(float4*)(kvs + pos) = *(const float4*)(kg + pos);
        }
        __syncthreads();

        // ---- Phase A: S = q k^T over h (packed over q-row pairs) ----
        u64 s2[4][8];   // s2[ip][j] = {S[tx*8+2ip][j], S[tx*8+2ip+1][j]}
        #pragma unroll
        for (int ip = 0; ip < 4; ip++)
            #pragma unroll
            for (int j = 0; j < 8; j++) s2[ip][j] = 0ull;

        #pragma unroll 2
        for (int h = 0; h < 128; h += 2) {
            // k for h and h+1: contiguous along h -> LDS.64, then dup halves
            float2 kp[8];
            #pragma unroll
            for (int j = 0; j < 8; j++)
                kp[j] = *(const float2*)(kvs + (ty * 8 + j) * 128 + h);

            {   // h
                const ulonglong2* qp = (const ulonglong2*)
                    (qs + h * 128 + ((tx ^ ((h >> 2) & 15)) << 3));
                ulonglong2 qa = qp[0], qb = qp[1];
                u64 a2[4] = {qa.x, qa.y, qb.x, qb.y};
                #pragma unroll
                for (int j = 0; j < 8; j++) {
                    u64 kb = f2dup(kp[j].x);
                    #pragma unroll
                    for (int ip = 0; ip < 4; ip++)
                        s2[ip][j] = f2fma(a2[ip], kb, s2[ip][j]);
                }
            }
            {   // h+1 (same swizzle key: 2-aligned pair never straddles 4-boundary)
                const ulonglong2* qp = (const ulonglong2*)
                    (qs + (h + 1) * 128 + ((tx ^ (((h + 1) >> 2) & 15)) << 3));
                ulonglong2 qa = qp[0], qb = qp[1];
                u64 a2[4] = {qa.x, qa.y, qb.x, qb.y};
                #pragma unroll
                for (int j = 0; j < 8; j++) {
                    u64 kb = f2dup(kp[j].y);
                    #pragma unroll
                    for (int ip = 0; ip < 4; ip++)
                        s2[ip][j] = f2fma(a2[ip], kb, s2[ip][j]);
                }
            }
        }

        // decay (+ causal mask on diagonal tile only), store S^T[m][n]
        {
            const int D = (n0 - m0) + tx * 8 - ty * 8;   // d = D + i - j
            const float base = SCALE * exp2f((float)D * L2G);
            float fi[8];
            #pragma unroll
            for (int i = 0; i < 8; i++) fi[i] = base * gp[i];

            if (mt < bx) {                               // always causal (D >= 8)
                u64 fi2[4];
                #pragma unroll
                for (int ip = 0; ip < 4; ip++) fi2[ip] = f2pack(fi[2*ip], fi[2*ip+1]);
                #pragma unroll
                for (int j = 0; j < 8; j++) {
                    u64 gj = f2dup(gn[j]);
                    u64 w[4];
                    #pragma unroll
                    for (int ip = 0; ip < 4; ip++)
                        w[ip] = f2mul(f2mul(s2[ip][j], fi2[ip]), gj);
                    ulonglong2* p = (ulonglong2*)(ss + (ty * 8 + j) * 128 + tx * 8);
                    p[0] = make_ulonglong2(w[0], w[1]);
                    p[1] = make_ulonglong2(w[2], w[3]);
                }
            } else {                                     // diagonal: scalar masked
                float s[8][8];
                #pragma unroll
                for (int ip = 0; ip < 4; ip++)
                    #pragma unroll
                    for (int j = 0; j < 8; j++) {
                        float2 t = f2unpack(s2[ip][j]);
                        s[2*ip][j]   = t.x;
                        s[2*ip+1][j] = t.y;
                    }
                #pragma unroll
                for (int j = 0; j < 8; j++) {
                    float g = gn[j];
                    float w[8];
                    #pragma unroll
                    for (int i = 0; i < 8; i++)
                        w[i] = (D + i - j >= 0) ? s[i][j] * fi[i] * g : 0.0f;
                    float* p = ss + (ty * 8 + j) * 128 + tx * 8;
                    *(float4*)p       = make_float4(w[0], w[1], w[2], w[3]);
                    *(float4*)(p + 4) = make_float4(w[4], w[5], w[6], w[7]);
                }
            }
        }
        __syncthreads();   // all S^T written, all k reads done

        // v tile -> kvs
        const float* vg = g_v + ((size_t)b * TT + m0) * HH;
        #pragma unroll
        for (int i = 0; i < 16; i++) {
            int pos = (tid + i * 256) * 4;
            *(float4*)(kvs + pos) = *(const float4*)(vg + pos);
        }
        __syncthreads();

        // ---- Phase B: O += S v (packed over h-col pairs) ----
        #pragma unroll 4
        for (int m = 0; m < 128; ++m) {
            float4 a0 = *(const float4*)(ss + m * 128 + tx * 8);     // 4-way .128
            float4 a1 = *(const float4*)(ss + m * 128 + tx * 8 + 4);
            u64 ad[8] = {f2dup(a0.x), f2dup(a0.y), f2dup(a0.z), f2dup(a0.w),
                         f2dup(a1.x), f2dup(a1.y), f2dup(a1.z), f2dup(a1.w)};
            const ulonglong2* vp = (const ulonglong2*)(kvs + m * 128 + ty * 8);
            ulonglong2 v0 = vp[0], v1 = vp[1];          // 2-addr broadcast
            u64 b2[4] = {v0.x, v0.y, v1.x, v1.y};
            #pragma unroll
            for (int i = 0; i < 8; i++)
                #pragma unroll
                for (int p = 0; p < 4; p++)
                    o2[i][p] = f2fma(ad[i], b2[p], o2[i][p]);
        }
    }

    // out[n0 + tx*8+i][ty*8 + 2p..2p+1]
    float* og = out + ((size_t)b * TT + n0) * HH;
    #pragma unroll
    for (int i = 0; i < 8; i++) {
        ulonglong2* op = (ulonglong2*)(og + (size_t)(tx * 8 + i) * 128 + ty * 8);
        op[0] = make_ulonglong2(o2[i][0], o2[i][1]);
        op[1] = make_ulonglong2(o2[i][2], o2[i][3]);
    }
}

extern "C" void kernel_launch(void* const* d_in, const int* in_sizes, int n_in,
                              void* d_out, int out_size)
{
    const float* x  = (const float*)d_in[0];
    const float* Wq = (const float*)d_in[1];
    const float* Wk = (const float*)d_in[2];
    const float* Wv = (const float*)d_in[3];
    float* out = (float*)d_out;
    (void)in_sizes; (void)n_in; (void)out_size;

    const int qkv_smem  = 16384 * (int)sizeof(float);     // 64 KB
    const int attn_smem = 3 * 16384 * (int)sizeof(float); // 192 KB

    cudaFuncSetAttribute(qkv_kernel,
        cudaFuncAttributeMaxDynamicSharedMemorySize, qkv_smem);
    cudaFuncSetAttribute(attn_kernel,
        cudaFuncAttributeMaxDynamicSharedMemorySize, attn_smem);

    dim3 g1((BB * TT) / 128, 3);
    qkv_kernel<<<g1, 256, qkv_smem>>>(x, Wq, Wk, Wv);

    dim3 g2(TT / 128, BB);
    attn_kernel<<<g2, 256, attn_smem>>>(out);
}

// round 13
// speedup vs baseline: 1.1086x; 1.1086x over previous
#include <cuda_runtime.h>

#define BB 4
#define TT 4096
#define CC 1024
#define HH 128
#define SCALE 0.03125f              // C^-0.5 = 1/32
#define GAMMA 0.96875f
#define INVG  (1.0f / 0.96875f)
#define L2G  (-0.0458036929f)       // log2(0.96875)
#define NPAST 4                     // past key tiles of 128; dropped mass ~1e-7 rel

typedef unsigned long long u64;

// packed fp32x2 helpers (verified working on this toolchain in R7)
__device__ __forceinline__ u64 f2pack(float lo, float hi) {
    u64 r; asm("mov.b64 %0, {%1, %2};" : "=l"(r) : "f"(lo), "f"(hi)); return r;
}
__device__ __forceinline__ u64 f2dup(float v) {
    u64 r; asm("mov.b64 %0, {%1, %1};" : "=l"(r) : "f"(v)); return r;
}
__device__ __forceinline__ u64 f2fma(u64 a, u64 b, u64 c) {
    u64 d; asm("fma.rn.f32x2 %0, %1, %2, %3;" : "=l"(d) : "l"(a), "l"(b), "l"(c)); return d;
}
__device__ __forceinline__ u64 f2mul(u64 a, u64 b) {
    u64 d; asm("mul.rn.f32x2 %0, %1, %2;" : "=l"(d) : "l"(a), "l"(b)); return d;
}
__device__ __forceinline__ float2 f2unpack(u64 v) {
    float lo, hi; asm("mov.b64 {%0, %1}, %2;" : "=f"(lo), "=f"(hi) : "l"(v));
    return make_float2(lo, hi);
}

// Scratch for q,k,v projections: [B*T, H] each. No allocation APIs.
__device__ float g_q[BB * TT * HH];
__device__ float g_k[BB * TT * HH];
__device__ float g_v[BB * TT * HH];

__device__ __forceinline__ void cp_async16(float* s, const float* g) {
    unsigned sa = (unsigned)__cvta_generic_to_shared(s);
    asm volatile("cp.async.ca.shared.global [%0], [%1], 16;\n" :: "r"(sa), "l"(g));
}
__device__ __forceinline__ void cp_commit() {
    asm volatile("cp.async.commit_group;\n");
}
template <int N>
__device__ __forceinline__ void cp_wait() {
    asm volatile("cp.async.wait_group %0;\n" :: "n"(N));
}

// ---------------------------------------------------------------------------
// QKV projection GEMM: out[16384, 128] = x[16384, 1024] @ W[1024, 128]
// grid (128 row-tiles, 3 weights), 256 threads, 8x8 micro via f32x2.
// Bank fixes vs R7: x tile stored with row-bit3 column swizzle (broadcast
// pairs Δrow=8 now hit different banks); W fragment = two 4-word blocks at
// cols 4tx and 64+4tx (bank quadrant tx mod 8 -> 2-phase optimal).
// ---------------------------------------------------------------------------
__global__ __launch_bounds__(256, 2) void qkv_kernel(
    const float* __restrict__ x, const float* __restrict__ Wq,
    const float* __restrict__ Wk, const float* __restrict__ Wv)
{
    extern __shared__ float sm[];
    float* xs = sm;               // [2][128][32], col-swizzled by row bit3
    float* ws = sm + 2 * 4096;    // [2][32][128]

    const float* W    = (blockIdx.y == 0) ? Wq : (blockIdx.y == 1 ? Wk : Wv);
    float*       outp = (blockIdx.y == 0) ? g_q : (blockIdx.y == 1 ? g_k : g_v);

    const int row0 = blockIdx.x * 128;
    const int tid  = threadIdx.x;
    const int tx   = tid & 15;
    const int ty   = tid >> 4;

    auto issue = [&](int kt, int buf) {
        const int k0 = kt * 32;
        #pragma unroll
        for (int i = 0; i < 4; i++) {          // x tile: 128x32 floats
            int idx = tid + i * 256;
            int r = idx >> 3, kq = (idx & 7) << 2;
            int kqs = kq ^ (((r >> 3) & 1) << 2);      // row-bit3 col swizzle
            cp_async16(xs + buf * 4096 + r * 32 + kqs,
                       x + (size_t)(row0 + r) * CC + k0 + kq);
        }
        #pragma unroll
        for (int i = 0; i < 4; i++) {          // W tile: 32x128 floats
            int idx = tid + i * 256;
            int kr = idx >> 5, cq = (idx & 31) << 2;
            cp_async16(ws + buf * 4096 + kr * 128 + cq,
                       W + (size_t)(k0 + kr) * HH + cq);
        }
        cp_commit();
    };

    u64 acc2[8][4];   // rows ty*8+i ; col pairs {4tx,4tx+1},{4tx+2,3},{64+4tx..}
    #pragma unroll
    for (int i = 0; i < 8; i++)
        #pragma unroll
        for (int p = 0; p < 4; p++) acc2[i][p] = 0ull;

    const int xsw = (ty & 1) << 2;   // row-bit3 of (ty*8+i) = ty&1, all i<8

    issue(0, 0);
    for (int kt = 0; kt < CC / 32; ++kt) {
        const int cur = kt & 1;
        if (kt + 1 < CC / 32) { issue(kt + 1, cur ^ 1); cp_wait<1>(); }
        else                  { cp_wait<0>(); }
        __syncthreads();

        const float* xb = xs + cur * 4096;
        const float* wb = ws + cur * 4096;
        #pragma unroll
        for (int kk = 0; kk < 32; kk += 2) {
            u64 a2lo[8], a2hi[8];
            #pragma unroll
            for (int i = 0; i < 8; i++) {      // conflict-free 2-addr broadcast
                float2 xv = *(const float2*)(xb + (ty * 8 + i) * 32 + (kk ^ xsw));
                a2lo[i] = f2dup(xv.x);
                a2hi[i] = f2dup(xv.y);
            }
            {
                const ulonglong2 bl0 = *(const ulonglong2*)(wb + kk * 128 + tx * 4);
                const ulonglong2 bl1 = *(const ulonglong2*)(wb + kk * 128 + 64 + tx * 4);
                u64 b2[4] = {bl0.x, bl0.y, bl1.x, bl1.y};
                #pragma unroll
                for (int i = 0; i < 8; i++)
                    #pragma unroll
                    for (int p = 0; p < 4; p++)
                        acc2[i][p] = f2fma(a2lo[i], b2[p], acc2[i][p]);
            }
            {
                const ulonglong2 bl0 = *(const ulonglong2*)(wb + (kk + 1) * 128 + tx * 4);
                const ulonglong2 bl1 = *(const ulonglong2*)(wb + (kk + 1) * 128 + 64 + tx * 4);
                u64 b2[4] = {bl0.x, bl0.y, bl1.x, bl1.y};
                #pragma unroll
                for (int i = 0; i < 8; i++)
                    #pragma unroll
                    for (int p = 0; p < 4; p++)
                        acc2[i][p] = f2fma(a2hi[i], b2[p], acc2[i][p]);
            }
        }
        __syncthreads();
    }

    #pragma unroll
    for (int i = 0; i < 8; i++) {
        float* orow = outp + (size_t)(row0 + ty * 8 + i) * HH;
        *(ulonglong2*)(orow + tx * 4)      = make_ulonglong2(acc2[i][0], acc2[i][1]);
        *(ulonglong2*)(orow + 64 + tx * 4) = make_ulonglong2(acc2[i][2], acc2[i][3]);
    }
}

// ---------------------------------------------------------------------------
// Banded retention, 128-row Q tile per CTA, <=5 key tiles, f32x2 packed.
// Thread rows: n in {4tx..4tx+3} U {64+4tx..64+4tx+3}; cols m/h = ty*8..+7.
// Bank fixes vs R7:
//  - q^T tile: 4-word-block swizzle; reads = 2x LDS.128 at 2 phases (optimal)
//  - kvs: row-bit3 column swizzle; k broadcast pairs now conflict-free
//  - ss fragments at 4tx / 64+4tx: 2-phase loads, 4-phase (data-floor) stores
// smem 192 KB -> 1 CTA/SM, 128 CTAs = one wave.
// ---------------------------------------------------------------------------
__global__ __launch_bounds__(256, 1) void attn_kernel(float* __restrict__ out)
{
    extern __shared__ float sm[];
    float* qs  = sm;            // q^T [128 h][128 n], 4-block swizzled
    float* kvs = sm + 16384;    // [128][128] (k, then v), col-swizzled by row bit3
    float* ss  = sm + 32768;    // S^T: [128 m][128 n], plain

    const int b   = blockIdx.y;
    const int bx  = blockIdx.x;
    const int n0  = bx * 128;
    const int tid = threadIdx.x;
    const int tx  = tid & 15;
    const int ty  = tid >> 4;

    // q load + transpose (once per CTA). Placement: value (h, n=r) stored at
    // qs[h*128 + ((r>>2 ^ (h>>2)&31)<<2) + (r&3)]
    const float* qg = g_q + ((size_t)b * TT + n0) * HH;
    #pragma unroll
    for (int i = 0; i < 16; i++) {
        int idx = tid + i * 256;
        int r = idx >> 5, c = (idx & 31) << 2;
        float4 v4 = *(const float4*)(qg + r * 128 + c);
        float vals[4] = {v4.x, v4.y, v4.z, v4.w};
        #pragma unroll
        for (int k = 0; k < 4; k++) {
            int h = c + k;
            qs[h * 128 + ((((r >> 2) ^ ((h >> 2) & 31)) << 2) | (r & 3))] = vals[k];
        }
    }

    u64 o2[8][4];   // O[row i of R(tx)][h pair p: ty*8+2p, +2p+1]
    #pragma unroll
    for (int i = 0; i < 8; i++)
        #pragma unroll
        for (int p = 0; p < 4; p++) o2[i][p] = 0ull;

    float gp[8], gn[8];
    gp[0] = 1.0f; gn[0] = 1.0f;
    #pragma unroll
    for (int i = 1; i < 8; i++) { gp[i] = gp[i-1] * GAMMA; gn[i] = gn[i-1] * INVG; }
    const float g64 = exp2f(64.0f * L2G);   // gamma^64

    const int ksw = (ty & 1) << 4;   // kvs col-swizzle key for rows ty*8+j

    int mt0 = bx - NPAST; if (mt0 < 0) mt0 = 0;

    for (int mt = mt0; mt <= bx; ++mt) {
        const int m0 = mt * 128;
        __syncthreads();   // q stores visible (iter0) / prev phase-B reads done

        // k tile -> kvs with row-bit3 col swizzle
        const float* kg = g_k + ((size_t)b * TT + m0) * HH;
        #pragma unroll
        for (int i = 0; i < 16; i++) {
            int idx = tid + i * 256;
            int r = idx >> 5, c4 = (idx & 31) << 2;
            *(float4*)(kvs + r * 128 + (c4 ^ ((r & 8) << 1))) =
                *(const float4*)(kg + r * 128 + c4);
        }
        __syncthreads();

        // ---- Phase A: S = q k^T over h ----
        u64 s2[4][8];   // s2[ip][j]: n-pairs of R(tx) x m = ty*8+j
        #pragma unroll
        for (int ip = 0; ip < 4; ip++)
            #pragma unroll
            for (int j = 0; j < 8; j++) s2[ip][j] = 0ull;

        #pragma unroll 2
        for (int h = 0; h < 128; h += 2) {
            float2 kp[8];   // k[(ty*8+j)][h..h+1], conflict-free broadcasts
            #pragma unroll
            for (int j = 0; j < 8; j++)
                kp[j] = *(const float2*)(kvs + (ty * 8 + j) * 128 + (h ^ ksw));

            {   // h
                const int sh = (h >> 2) & 31;
                const float* qrow = qs + h * 128;
                ulonglong2 qa = *(const ulonglong2*)(qrow + ((tx ^ sh) << 2));
                ulonglong2 qb = *(const ulonglong2*)(qrow + (((16 + tx) ^ sh) << 2));
                u64 a2[4] = {qa.x, qa.y, qb.x, qb.y};
                #pragma unroll
                for (int j = 0; j < 8; j++) {
                    u64 kb = f2dup(kp[j].x);
                    #pragma unroll
                    for (int ip = 0; ip < 4; ip++)
                        s2[ip][j] = f2fma(a2[ip], kb, s2[ip][j]);
                }
            }
            {   // h+1 (same 4-block swizzle key within the aligned pair)
                const int sh = ((h + 1) >> 2) & 31;
                const float* qrow = qs + (h + 1) * 128;
                ulonglong2 qa = *(const ulonglong2*)(qrow + ((tx ^ sh) << 2));
                ulonglong2 qb = *(const ulonglong2*)(qrow + (((16 + tx) ^ sh) << 2));
                u64 a2[4] = {qa.x, qa.y, qb.x, qb.y};
                #pragma unroll
                for (int j = 0; j < 8; j++) {
                    u64 kb = f2dup(kp[j].y);
                    #pragma unroll
                    for (int ip = 0; ip < 4; ip++)
                        s2[ip][j] = f2fma(a2[ip], kb, s2[ip][j]);
                }
            }
        }

        // decay (+ causal mask on diagonal tile only), store S^T[m][n]
        {
            const int D0 = (n0 - m0) + tx * 4 - ty * 8;   // d = D0 + off_i - j
            const float base = SCALE * exp2f((float)D0 * L2G);
            float fi[8];
            #pragma unroll
            for (int i = 0; i < 4; i++) { fi[i] = base * gp[i]; fi[i + 4] = base * g64 * gp[i]; }

            if (mt < bx) {                               // fully causal
                u64 fi2[4];
                #pragma unroll
                for (int ip = 0; ip < 4; ip++) fi2[ip] = f2pack(fi[2*ip], fi[2*ip+1]);
                #pragma unroll
                for (int j = 0; j < 8; j++) {
                    u64 gj = f2dup(gn[j]);
                    u64 w[4];
                    #pragma unroll
                    for (int ip = 0; ip < 4; ip++)
                        w[ip] = f2mul(f2mul(s2[ip][j], fi2[ip]), gj);
                    float* p = ss + (ty * 8 + j) * 128;
                    *(ulonglong2*)(p + tx * 4)      = make_ulonglong2(w[0], w[1]);
                    *(ulonglong2*)(p + 64 + tx * 4) = make_ulonglong2(w[2], w[3]);
                }
            } else {                                     // diagonal: scalar masked
                float s[8][8];
                #pragma unroll
                for (int ip = 0; ip < 4; ip++)
                    #pragma unroll
                    for (int j = 0; j < 8; j++) {
                        float2 t = f2unpack(s2[ip][j]);
                        s[2*ip][j]   = t.x;
                        s[2*ip+1][j] = t.y;
                    }
                #pragma unroll
                for (int j = 0; j < 8; j++) {
                    float g = gn[j];
                    float w[8];
                    #pragma unroll
                    for (int i = 0; i < 8; i++) {
                        int off = (i < 4) ? i : (60 + i);   // 64 + (i-4)
                        w[i] = (D0 + off - j >= 0) ? s[i][j] * fi[i] * g : 0.0f;
                    }
                    float* p = ss + (ty * 8 + j) * 128;
                    *(float4*)(p + tx * 4)      = make_float4(w[0], w[1], w[2], w[3]);
                    *(float4*)(p + 64 + tx * 4) = make_float4(w[4], w[5], w[6], w[7]);
                }
            }
        }
        __syncthreads();   // all S^T written, all k reads done

        // v tile -> kvs (same col swizzle)
        const float* vg = g_v + ((size_t)b * TT + m0) * HH;
        #pragma unroll
        for (int i = 0; i < 16; i++) {
            int idx = tid + i * 256;
            int r = idx >> 5, c4 = (idx & 31) << 2;
            *(float4*)(kvs + r * 128 + (c4 ^ ((r & 8) << 1))) =
                *(const float4*)(vg + r * 128 + c4);
        }
        __syncthreads();

        // ---- Phase B: O += S v ----
        #pragma unroll 4
        for (int m = 0; m < 128; ++m) {
            float4 a0 = *(const float4*)(ss + m * 128 + tx * 4);       // 2-phase
            float4 a1 = *(const float4*)(ss + m * 128 + 64 + tx * 4);
            u64 ad[8] = {f2dup(a0.x), f2dup(a0.y), f2dup(a0.z), f2dup(a0.w),
                         f2dup(a1.x), f2dup(a1.y), f2dup(a1.z), f2dup(a1.w)};
            const int vsw = (m & 8) << 1;
            const float* vrow = kvs + m * 128;
            ulonglong2 v0 = *(const ulonglong2*)(vrow + ((ty * 8) ^ vsw));
            ulonglong2 v1 = *(const ulonglong2*)(vrow + (((ty * 8) ^ vsw) + 4));
            u64 b2[4] = {v0.x, v0.y, v1.x, v1.y};
            #pragma unroll
            for (int i = 0; i < 8; i++)
                #pragma unroll
                for (int p = 0; p < 4; p++)
                    o2[i][p] = f2fma(ad[i], b2[p], o2[i][p]);
        }
    }

    // out rows R(tx), cols ty*8..+7
    float* og = out + ((size_t)b * TT + n0) * HH;
    #pragma unroll
    for (int i = 0; i < 8; i++) {
        int nloc = (i < 4) ? (tx * 4 + i) : (64 + tx * 4 + i - 4);
        ulonglong2* op = (ulonglong2*)(og + (size_t)nloc * 128 + ty * 8);
        op[0] = make_ulonglong2(o2[i][0], o2[i][1]);
        op[1] = make_ulonglong2(o2[i][2], o2[i][3]);
    }
}

extern "C" void kernel_launch(void* const* d_in, const int* in_sizes, int n_in,
                              void* d_out, int out_size)
{
    const float* x  = (const float*)d_in[0];
    const float* Wq = (const float*)d_in[1];
    const float* Wk = (const float*)d_in[2];
    const float* Wv = (const float*)d_in[3];
    float* out = (float*)d_out;
    (void)in_sizes; (void)n_in; (void)out_size;

    const int qkv_smem  = 16384 * (int)sizeof(float);     // 64 KB
    const int attn_smem = 3 * 16384 * (int)sizeof(float); // 192 KB

    cudaFuncSetAttribute(qkv_kernel,
        cudaFuncAttributeMaxDynamicSharedMemorySize, qkv_smem);
    cudaFuncSetAttribute(attn_kernel,
        cudaFuncAttributeMaxDynamicSharedMemorySize, attn_smem);

    dim3 g1((BB * TT) / 128, 3);
    qkv_kernel<<<g1, 256, qkv_smem>>>(x, Wq, Wk, Wv);

    dim3 g2(TT / 128, BB);
    attn_kernel<<<g2, 256, attn_smem>>>(out);
}

// round 14
// speedup vs baseline: 1.1094x; 1.0006x over previous
#include <cuda_runtime.h>

#define BB 4
#define TT 4096
#define CC 1024
#define HH 128
#define SCALE 0.03125f              // C^-0.5 = 1/32
#define GAMMA 0.96875f
#define INVG  (1.0f / 0.96875f)
#define L2G  (-0.0458036929f)       // log2(0.96875)
#define NPAST 4                     // past key tiles of 128; dropped mass ~1e-7 rel
#define QTILES (128 * 3)            // qkv tiles: 128 row-tiles x 3 weights

typedef unsigned long long u64;

// packed fp32x2 helpers (verified working on this toolchain R7/R13)
__device__ __forceinline__ u64 f2pack(float lo, float hi) {
    u64 r; asm("mov.b64 %0, {%1, %2};" : "=l"(r) : "f"(lo), "f"(hi)); return r;
}
__device__ __forceinline__ u64 f2dup(float v) {
    u64 r; asm("mov.b64 %0, {%1, %1};" : "=l"(r) : "f"(v)); return r;
}
__device__ __forceinline__ u64 f2fma(u64 a, u64 b, u64 c) {
    u64 d; asm("fma.rn.f32x2 %0, %1, %2, %3;" : "=l"(d) : "l"(a), "l"(b), "l"(c)); return d;
}
__device__ __forceinline__ u64 f2mul(u64 a, u64 b) {
    u64 d; asm("mul.rn.f32x2 %0, %1, %2;" : "=l"(d) : "l"(a), "l"(b)); return d;
}
__device__ __forceinline__ float2 f2unpack(u64 v) {
    float lo, hi; asm("mov.b64 {%0, %1}, %2;" : "=f"(lo), "=f"(hi) : "l"(v));
    return make_float2(lo, hi);
}

// Scratch for q,k,v projections: [B*T, H] each. No allocation APIs.
__device__ float g_q[BB * TT * HH];
__device__ float g_k[BB * TT * HH];
__device__ float g_v[BB * TT * HH];
__device__ unsigned g_ticket;

__device__ __forceinline__ void cp_async16(float* s, const float* g) {
    unsigned sa = (unsigned)__cvta_generic_to_shared(s);
    asm volatile("cp.async.ca.shared.global [%0], [%1], 16;\n" :: "r"(sa), "l"(g));
}
__device__ __forceinline__ void cp_commit() {
    asm volatile("cp.async.commit_group;\n");
}
template <int N>
__device__ __forceinline__ void cp_wait() {
    asm volatile("cp.async.wait_group %0;\n" :: "n"(N));
}

__global__ void reset_ticket_kernel() { g_ticket = 0; }

// ---------------------------------------------------------------------------
// QKV projection GEMM (persistent + dynamic ticket over 384 tiles):
// out[16384, 128] = x[16384, 1024] @ W[1024, 128]
// 296 CTAs x 256 threads, 2 CTAs/SM; inner K-loop identical to R13 (passing).
// ---------------------------------------------------------------------------
__global__ __launch_bounds__(256, 2) void qkv_kernel(
    const float* __restrict__ x, const float* __restrict__ Wq,
    const float* __restrict__ Wk, const float* __restrict__ Wv)
{
    extern __shared__ float sm[];
    float* xs = sm;               // [2][128][32], col-swizzled by row bit3
    float* ws = sm + 2 * 4096;    // [2][32][128]
    __shared__ unsigned s_tile;

    const int tid  = threadIdx.x;
    const int tx   = tid & 15;
    const int ty   = tid >> 4;
    const int xsw = (ty & 1) << 2;   // row-bit3 of (ty*8+i) = ty&1, all i<8

    for (;;) {
        if (tid == 0) s_tile = atomicAdd(&g_ticket, 1u);
        __syncthreads();
        const unsigned t = s_tile;
        if (t >= QTILES) break;

        const int yw   = t >> 7;           // 0..2
        const int row0 = (t & 127) * 128;
        const float* W    = (yw == 0) ? Wq : (yw == 1 ? Wk : Wv);
        float*       outp = (yw == 0) ? g_q : (yw == 1 ? g_k : g_v);

        auto issue = [&](int kt, int buf) {
            const int k0 = kt * 32;
            #pragma unroll
            for (int i = 0; i < 4; i++) {          // x tile: 128x32 floats
                int idx = tid + i * 256;
                int r = idx >> 3, kq = (idx & 7) << 2;
                int kqs = kq ^ (((r >> 3) & 1) << 2);      // row-bit3 col swizzle
                cp_async16(xs + buf * 4096 + r * 32 + kqs,
                           x + (size_t)(row0 + r) * CC + k0 + kq);
            }
            #pragma unroll
            for (int i = 0; i < 4; i++) {          // W tile: 32x128 floats
                int idx = tid + i * 256;
                int kr = idx >> 5, cq = (idx & 31) << 2;
                cp_async16(ws + buf * 4096 + kr * 128 + cq,
                           W + (size_t)(k0 + kr) * HH + cq);
            }
            cp_commit();
        };

        u64 acc2[8][4];
        #pragma unroll
        for (int i = 0; i < 8; i++)
            #pragma unroll
            for (int p = 0; p < 4; p++) acc2[i][p] = 0ull;

        issue(0, 0);
        for (int kt = 0; kt < CC / 32; ++kt) {
            const int cur = kt & 1;
            if (kt + 1 < CC / 32) { issue(kt + 1, cur ^ 1); cp_wait<1>(); }
            else                  { cp_wait<0>(); }
            __syncthreads();

            const float* xb = xs + cur * 4096;
            const float* wb = ws + cur * 4096;
            #pragma unroll
            for (int kk = 0; kk < 32; kk += 2) {
                u64 a2lo[8], a2hi[8];
                #pragma unroll
                for (int i = 0; i < 8; i++) {      // conflict-free 2-addr broadcast
                    float2 xv = *(const float2*)(xb + (ty * 8 + i) * 32 + (kk ^ xsw));
                    a2lo[i] = f2dup(xv.x);
                    a2hi[i] = f2dup(xv.y);
                }
                {
                    const ulonglong2 bl0 = *(const ulonglong2*)(wb + kk * 128 + tx * 4);
                    const ulonglong2 bl1 = *(const ulonglong2*)(wb + kk * 128 + 64 + tx * 4);
                    u64 b2[4] = {bl0.x, bl0.y, bl1.x, bl1.y};
                    #pragma unroll
                    for (int i = 0; i < 8; i++)
                        #pragma unroll
                        for (int p = 0; p < 4; p++)
                            acc2[i][p] = f2fma(a2lo[i], b2[p], acc2[i][p]);
                }
                {
                    const ulonglong2 bl0 = *(const ulonglong2*)(wb + (kk + 1) * 128 + tx * 4);
                    const ulonglong2 bl1 = *(const ulonglong2*)(wb + (kk + 1) * 128 + 64 + tx * 4);
                    u64 b2[4] = {bl0.x, bl0.y, bl1.x, bl1.y};
                    #pragma unroll
                    for (int i = 0; i < 8; i++)
                        #pragma unroll
                        for (int p = 0; p < 4; p++)
                            acc2[i][p] = f2fma(a2hi[i], b2[p], acc2[i][p]);
                }
            }
            __syncthreads();
        }

        #pragma unroll
        for (int i = 0; i < 8; i++) {
            float* orow = outp + (size_t)(row0 + ty * 8 + i) * HH;
            *(ulonglong2*)(orow + tx * 4)      = make_ulonglong2(acc2[i][0], acc2[i][1]);
            *(ulonglong2*)(orow + 64 + tx * 4) = make_ulonglong2(acc2[i][2], acc2[i][3]);
        }
        // loop continues; next iteration's s_tile write is safe (t is in regs),
        // smem tile reuse is fenced by the top __syncthreads().
    }
}

// ---------------------------------------------------------------------------
// Banded retention, 128-row Q tile per CTA, <=5 key tiles, f32x2 packed.
// 512 threads (16 warps/SM) for latency hiding — R13 measured occ=12.4%,
// fma=49% with L1 also low => latency-bound; this doubles resident warps.
// Rows per thread: n in {4tx..+3} U {64+4tx..+3}; cols m/h = 4tz..+3 (tz=tid>>4).
// kvs col-swizzle now keyed on row BIT2 (in-warp tz pair differs in bit2).
// smem 192 KB -> 1 CTA/SM, 128 CTAs.
// ---------------------------------------------------------------------------
__global__ __launch_bounds__(512, 1) void attn_kernel(float* __restrict__ out)
{
    extern __shared__ float sm[];
    float* qs  = sm;            // q^T [128 h][128 n], 4-block swizzled
    float* kvs = sm + 16384;    // [128][128] (k, then v), col-swizzled by row bit2
    float* ss  = sm + 32768;    // S^T: [128 m][128 n], plain

    const int b   = blockIdx.y;
    const int bx  = blockIdx.x;
    const int n0  = bx * 128;
    const int tid = threadIdx.x;
    const int tx  = tid & 15;
    const int tz  = tid >> 4;        // 0..31

    // q load + transpose (once per CTA): value (h, n=r) at
    // qs[h*128 + ((r>>2 ^ (h>>2)&31)<<2) + (r&3)]
    const float* qg = g_q + ((size_t)b * TT + n0) * HH;
    #pragma unroll
    for (int i = 0; i < 8; i++) {
        int idx = tid + i * 512;
        int r = idx >> 5, c = (idx & 31) << 2;
        float4 v4 = *(const float4*)(qg + r * 128 + c);
        float vals[4] = {v4.x, v4.y, v4.z, v4.w};
        #pragma unroll
        for (int k = 0; k < 4; k++) {
            int h = c + k;
            qs[h * 128 + ((((r >> 2) ^ ((h >> 2) & 31)) << 2) | (r & 3))] = vals[k];
        }
    }

    u64 o2[8][2];   // O[row i of R(tx)][h pair p: 4tz+2p, +2p+1]
    #pragma unroll
    for (int i = 0; i < 8; i++) { o2[i][0] = 0ull; o2[i][1] = 0ull; }

    float gp[4], gn[4];
    gp[0] = 1.0f; gn[0] = 1.0f;
    #pragma unroll
    for (int i = 1; i < 4; i++) { gp[i] = gp[i-1] * GAMMA; gn[i] = gn[i-1] * INVG; }
    const float g64 = exp2f(64.0f * L2G);   // gamma^64

    const int ksw = (tz & 1) << 4;   // kvs col-swizzle key for rows 4tz+j (bit2)

    int mt0 = bx - NPAST; if (mt0 < 0) mt0 = 0;

    for (int mt = mt0; mt <= bx; ++mt) {
        const int m0 = mt * 128;
        __syncthreads();   // q stores visible (iter0) / prev phase-B reads done

        // k tile -> kvs with row-bit2 col swizzle
        const float* kg = g_k + ((size_t)b * TT + m0) * HH;
        #pragma unroll
        for (int i = 0; i < 8; i++) {
            int idx = tid + i * 512;
            int r = idx >> 5, c4 = (idx & 31) << 2;
            *(float4*)(kvs + r * 128 + (c4 ^ ((r & 4) << 2))) =
                *(const float4*)(kg + r * 128 + c4);
        }
        __syncthreads();

        // ---- Phase A: S = q k^T over h ----
        u64 s2[4][4];   // s2[ip][j]: n-pairs of R(tx) x m = 4tz+j
        #pragma unroll
        for (int ip = 0; ip < 4; ip++)
            #pragma unroll
            for (int j = 0; j < 4; j++) s2[ip][j] = 0ull;

        #pragma unroll 2
        for (int h = 0; h < 128; h += 2) {
            float2 kp[4];   // k[(4tz+j)][h..h+1], conflict-free broadcasts
            #pragma unroll
            for (int j = 0; j < 4; j++)
                kp[j] = *(const float2*)(kvs + (tz * 4 + j) * 128 + (h ^ ksw));

            {   // h
                const int sh = (h >> 2) & 31;
                const float* qrow = qs + h * 128;
                ulonglong2 qa = *(const ulonglong2*)(qrow + ((tx ^ sh) << 2));
                ulonglong2 qb = *(const ulonglong2*)(qrow + (((16 + tx) ^ sh) << 2));
                u64 a2[4] = {qa.x, qa.y, qb.x, qb.y};
                #pragma unroll
                for (int j = 0; j < 4; j++) {
                    u64 kb = f2dup(kp[j].x);
                    #pragma unroll
                    for (int ip = 0; ip < 4; ip++)
                        s2[ip][j] = f2fma(a2[ip], kb, s2[ip][j]);
                }
            }
            {   // h+1 (same 4-block key within aligned pair)
                const int sh = ((h + 1) >> 2) & 31;
                const float* qrow = qs + (h + 1) * 128;
                ulonglong2 qa = *(const ulonglong2*)(qrow + ((tx ^ sh) << 2));
                ulonglong2 qb = *(const ulonglong2*)(qrow + (((16 + tx) ^ sh) << 2));
                u64 a2[4] = {qa.x, qa.y, qb.x, qb.y};
                #pragma unroll
                for (int j = 0; j < 4; j++) {
                    u64 kb = f2dup(kp[j].y);
                    #pragma unroll
                    for (int ip = 0; ip < 4; ip++)
                        s2[ip][j] = f2fma(a2[ip], kb, s2[ip][j]);
                }
            }
        }

        // decay (+ causal mask on diagonal tile only), store S^T[m][n]
        {
            const int D0 = (n0 - m0) + tx * 4 - tz * 4;   // d = D0 + off_i - j
            const float base = SCALE * exp2f((float)D0 * L2G);
            float fi[8];
            #pragma unroll
            for (int i = 0; i < 4; i++) { fi[i] = base * gp[i]; fi[i + 4] = base * g64 * gp[i]; }

            if (mt < bx) {                               // fully causal
                u64 fi2[4];
                #pragma unroll
                for (int ip = 0; ip < 4; ip++) fi2[ip] = f2pack(fi[2*ip], fi[2*ip+1]);
                #pragma unroll
                for (int j = 0; j < 4; j++) {
                    u64 gj = f2dup(gn[j]);
                    u64 w[4];
                    #pragma unroll
                    for (int ip = 0; ip < 4; ip++)
                        w[ip] = f2mul(f2mul(s2[ip][j], fi2[ip]), gj);
                    float* p = ss + (tz * 4 + j) * 128;
                    *(ulonglong2*)(p + tx * 4)      = make_ulonglong2(w[0], w[1]);
                    *(ulonglong2*)(p + 64 + tx * 4) = make_ulonglong2(w[2], w[3]);
                }
            } else {                                     // diagonal: scalar masked
                float s[8][4];
                #pragma unroll
                for (int ip = 0; ip < 4; ip++)
                    #pragma unroll
                    for (int j = 0; j < 4; j++) {
                        float2 t2 = f2unpack(s2[ip][j]);
                        s[2*ip][j]   = t2.x;
                        s[2*ip+1][j] = t2.y;
                    }
                #pragma unroll
                for (int j = 0; j < 4; j++) {
                    float g = gn[j];
                    float w[8];
                    #pragma unroll
                    for (int i = 0; i < 8; i++) {
                        int off = (i < 4) ? i : (60 + i);   // 64 + (i-4)
                        w[i] = (D0 + off - j >= 0) ? s[i][j] * fi[i] * g : 0.0f;
                    }
                    float* p = ss + (tz * 4 + j) * 128;
                    *(float4*)(p + tx * 4)      = make_float4(w[0], w[1], w[2], w[3]);
                    *(float4*)(p + 64 + tx * 4) = make_float4(w[4], w[5], w[6], w[7]);
                }
            }
        }
        __syncthreads();   // all S^T written, all k reads done

        // v tile -> kvs (same bit2 col swizzle)
        const float* vg = g_v + ((size_t)b * TT + m0) * HH;
        #pragma unroll
        for (int i = 0; i < 8; i++) {
            int idx = tid + i * 512;
            int r = idx >> 5, c4 = (idx & 31) << 2;
            *(float4*)(kvs + r * 128 + (c4 ^ ((r & 4) << 2))) =
                *(const float4*)(vg + r * 128 + c4);
        }
        __syncthreads();

        // ---- Phase B: O += S v ----
        #pragma unroll 4
        for (int m = 0; m < 128; ++m) {
            float4 a0 = *(const float4*)(ss + m * 128 + tx * 4);       // 2-phase
            float4 a1 = *(const float4*)(ss + m * 128 + 64 + tx * 4);
            u64 ad[8] = {f2dup(a0.x), f2dup(a0.y), f2dup(a0.z), f2dup(a0.w),
                         f2dup(a1.x), f2dup(a1.y), f2dup(a1.z), f2dup(a1.w)};
            const int vsw = (m & 4) << 2;
            ulonglong2 vv = *(const ulonglong2*)(kvs + m * 128 + ((tz * 4) ^ vsw));
            u64 b2[2] = {vv.x, vv.y};   // v[m][4tz..4tz+3]
            #pragma unroll
            for (int i = 0; i < 8; i++) {
                o2[i][0] = f2fma(ad[i], b2[0], o2[i][0]);
                o2[i][1] = f2fma(ad[i], b2[1], o2[i][1]);
            }
        }
    }

    // out rows R(tx), cols 4tz..+3
    float* og = out + ((size_t)b * TT + n0) * HH;
    #pragma unroll
    for (int i = 0; i < 8; i++) {
        int nloc = (i < 4) ? (tx * 4 + i) : (64 + tx * 4 + i - 4);
        *(ulonglong2*)(og + (size_t)nloc * 128 + tz * 4) =
            make_ulonglong2(o2[i][0], o2[i][1]);
    }
}

extern "C" void kernel_launch(void* const* d_in, const int* in_sizes, int n_in,
                              void* d_out, int out_size)
{
    const float* x  = (const float*)d_in[0];
    const float* Wq = (const float*)d_in[1];
    const float* Wk = (const float*)d_in[2];
    const float* Wv = (const float*)d_in[3];
    float* out = (float*)d_out;
    (void)in_sizes; (void)n_in; (void)out_size;

    const int qkv_smem  = 16384 * (int)sizeof(float);     // 64 KB
    const int attn_smem = 3 * 16384 * (int)sizeof(float); // 192 KB

    cudaFuncSetAttribute(qkv_kernel,
        cudaFuncAttributeMaxDynamicSharedMemorySize, qkv_smem);
    cudaFuncSetAttribute(attn_kernel,
        cudaFuncAttributeMaxDynamicSharedMemorySize, attn_smem);

    reset_ticket_kernel<<<1, 1>>>();

    qkv_kernel<<<296, 256, qkv_smem>>>(x, Wq, Wk, Wv);

    dim3 g2(TT / 128, BB);
    attn_kernel<<<g2, 512, attn_smem>>>(out);
}